// round 1
// baseline (speedup 1.0000x reference)
#include <cuda_runtime.h>
#include <cuda_bf16.h>
#include <math.h>

// Shapes (fixed by the problem)
#define B_   64
#define N_   128
#define F_   128
#define R_   64
#define H_   256
#define L_   3
#define ROWS (B_*N_)          // 8192

// ---------------- scratch (no allocations allowed) ----------------
__device__ float g_dsum[ROWS * R_];   // 2 MB
__device__ float g_x[ROWS * F_];      // 4 MB
__device__ float g_v[F_];
__device__ float g_cs;

// ---------------- Kernel A: d_sum[b,n,r] = sum_j distance[b,n,j,r] ----------------
// One block per (b,n) row: reduces 128x64 contiguous fp32 (32 KB) -> 64 floats.
__global__ void reduce_dist_kernel(const float* __restrict__ dist) {
    int row = blockIdx.x;                 // 0..8191
    int tid = threadIdx.x;                // 256 threads
    const float4* p = (const float4*)(dist + (size_t)row * (N_ * R_)); // 2048 float4
    float4 acc = make_float4(0.f, 0.f, 0.f, 0.f);
    #pragma unroll
    for (int t = 0; t < 8; t++) {
        float4 v = p[tid + t * 256];
        acc.x += v.x; acc.y += v.y; acc.z += v.z; acc.w += v.w;
    }
    __shared__ float4 s[256];
    s[tid] = acc;
    __syncthreads();
    // quad index of thread tid is (tid % 16); 16 threads share each r-quad
    if (tid < 16) {
        float4 a = s[tid];
        #pragma unroll
        for (int m = 1; m < 16; m++) {
            float4 b = s[tid + 16 * m];
            a.x += b.x; a.y += b.y; a.z += b.z; a.w += b.w;
        }
        ((float4*)(g_dsum + (size_t)row * R_))[tid] = a;
    }
}

// ---------------- Kernel B: fused 3-layer DTNN over 32-row tiles ----------------
// Block: 256 threads (ty = tid/32 in 0..7 -> 4 rows each; tx = tid%32).
// smem: Xs[32][128], Ps[32][256], Ds[32][64], weight staging (padded +4 floats
// per column to keep LDS.128 conflict-free).
#define CFPAD 132   // 128 + 4
#define DFPAD 68    // 64 + 4
#define FCPAD 260   // 256 + 4
#define WS_CF_FLOATS (64 * CFPAD)    // 8448 (also covers fc chunk: 32*260=8320)
#define WS_DF_FLOATS (64 * DFPAD)    // 4352
#define SMEM_B_FLOATS (32*128 + 32*256 + 32*64 + WS_CF_FLOATS + WS_DF_FLOATS)
#define SMEM_B_BYTES  (SMEM_B_FLOATS * 4)   // 108544 B

__global__ __launch_bounds__(256, 2)
void dtnn_layers_kernel(const float* __restrict__ x_in,
                        const float* __restrict__ Wcf_w, const float* __restrict__ Wcf_b,
                        const float* __restrict__ Wdf_w, const float* __restrict__ Wdf_b,
                        const float* __restrict__ Wfc_w) {
    extern __shared__ float sm[];
    float* Xs   = sm;                         // 32*128
    float* Ps   = Xs + 32 * 128;              // 32*256
    float* Ds   = Ps + 32 * 256;              // 32*64
    float* Ws   = Ds + 32 * 64;               // cf / fc staging
    float* Wsdf = Ws + WS_CF_FLOATS;          // df staging

    int tid = threadIdx.x;
    int tx = tid & 31, ty = tid >> 5;
    int row0 = blockIdx.x * 32;

    // load Xs (32x128) and Ds (32x64), fully coalesced
    {
        const float4* xg = (const float4*)(x_in + (size_t)row0 * F_);
        float4* Xs4 = (float4*)Xs;
        #pragma unroll
        for (int t = 0; t < 4; t++) Xs4[tid + t * 256] = xg[tid + t * 256];
        const float4* dg = (const float4*)(g_dsum + (size_t)row0 * R_);
        float4* Ds4 = (float4*)Ds;
        #pragma unroll
        for (int t = 0; t < 2; t++) Ds4[tid + t * 256] = dg[tid + t * 256];
    }
    __syncthreads();

    for (int l = 0; l < L_; l++) {
        const float* wcf = Wcf_w + (size_t)l * H_ * F_;
        const float* wdf = Wdf_w + (size_t)l * H_ * R_;
        const float* bcf = Wcf_b + (size_t)l * H_;
        const float* bdf = Wdf_b + (size_t)l * H_;
        const float* wfc = Wfc_w + (size_t)l * F_ * H_;

        // ---- cf & df GEMMs, fused product -> Ps ----
        for (int cb = 0; cb < H_; cb += 64) {
            // stage cf chunk: 64 cols x 128 k (contiguous slab) -> stride CFPAD
            {
                const float4* g = (const float4*)(wcf + (size_t)cb * F_);
                #pragma unroll
                for (int t = 0; t < 8; t++) {
                    int idx = tid + t * 256;           // 2048 float4
                    int cc = idx >> 5;                 // 32 f4 per col
                    int kq = idx & 31;
                    ((float4*)(Ws + cc * CFPAD))[kq] = g[idx];
                }
                const float4* gd = (const float4*)(wdf + (size_t)cb * R_);
                #pragma unroll
                for (int t = 0; t < 4; t++) {
                    int idx = tid + t * 256;           // 1024 float4
                    int cc = idx >> 4;                 // 16 f4 per col
                    int kq = idx & 15;
                    ((float4*)(Wsdf + cc * DFPAD))[kq] = gd[idx];
                }
            }
            __syncthreads();

            float accD[4][2] = {};
            float accC[4][2] = {};
            // df: K = 64
            #pragma unroll 4
            for (int k = 0; k < R_; k += 4) {
                float4 w0 = *(const float4*)(Wsdf + tx * DFPAD + k);
                float4 w1 = *(const float4*)(Wsdf + (tx + 32) * DFPAD + k);
                #pragma unroll
                for (int i = 0; i < 4; i++) {
                    float4 d = *(const float4*)(Ds + (ty * 4 + i) * R_ + k);
                    accD[i][0] += d.x * w0.x + d.y * w0.y + d.z * w0.z + d.w * w0.w;
                    accD[i][1] += d.x * w1.x + d.y * w1.y + d.z * w1.z + d.w * w1.w;
                }
            }
            // cf: K = 128
            #pragma unroll 4
            for (int k = 0; k < F_; k += 4) {
                float4 w0 = *(const float4*)(Ws + tx * CFPAD + k);
                float4 w1 = *(const float4*)(Ws + (tx + 32) * CFPAD + k);
                #pragma unroll
                for (int i = 0; i < 4; i++) {
                    float4 xv = *(const float4*)(Xs + (ty * 4 + i) * F_ + k);
                    accC[i][0] += xv.x * w0.x + xv.y * w0.y + xv.z * w0.z + xv.w * w0.w;
                    accC[i][1] += xv.x * w1.x + xv.y * w1.y + xv.z * w1.z + xv.w * w1.w;
                }
            }
            #pragma unroll
            for (int j = 0; j < 2; j++) {
                int c = cb + tx + 32 * j;
                float bc = __ldg(bcf + c);
                float bd = 128.0f * __ldg(bdf + c);
                #pragma unroll
                for (int i = 0; i < 4; i++) {
                    Ps[(ty * 4 + i) * H_ + c] = (accC[i][j] + bc) * (accD[i][j] + bd);
                }
            }
            __syncthreads();
        }

        // ---- h = P @ Wfc^T, x = h + tanh(h) -> Xs ----
        for (int fb = 0; fb < F_; fb += 32) {
            // stage fc chunk: 32 cols x 256 k (contiguous slab) -> stride FCPAD
            {
                const float4* g = (const float4*)(wfc + (size_t)fb * H_);
                #pragma unroll
                for (int t = 0; t < 8; t++) {
                    int idx = tid + t * 256;           // 2048 float4
                    int cc = idx >> 6;                 // 64 f4 per col
                    int kq = idx & 63;
                    ((float4*)(Ws + cc * FCPAD))[kq] = g[idx];
                }
            }
            __syncthreads();

            float acc3[4] = {};
            #pragma unroll 4
            for (int k = 0; k < H_; k += 4) {
                float4 w = *(const float4*)(Ws + tx * FCPAD + k);
                #pragma unroll
                for (int i = 0; i < 4; i++) {
                    float4 p = *(const float4*)(Ps + (ty * 4 + i) * H_ + k);
                    acc3[i] += p.x * w.x + p.y * w.y + p.z * w.z + p.w * w.w;
                }
            }
            int f = fb + tx;
            #pragma unroll
            for (int i = 0; i < 4; i++) {
                float h = acc3[i];
                Xs[(ty * 4 + i) * F_ + f] = h + tanhf(h);
            }
            __syncthreads();
        }
    }

    // write final x tile
    {
        float4* xo = (float4*)(g_x + (size_t)row0 * F_);
        const float4* Xs4 = (const float4*)Xs;
        #pragma unroll
        for (int t = 0; t < 4; t++) xo[tid + t * 256] = Xs4[tid + t * 256];
    }
}

// ---------------- Kernel C: fold head (v = out_w @ fc0_w, cs = out_w@fc0_b + out_b) ----------------
__global__ void fold_head_kernel(const float* __restrict__ fc0_w, const float* __restrict__ fc0_b,
                                 const float* __restrict__ out_w, const float* __restrict__ out_b) {
    int f = threadIdx.x;   // 128
    float a = 0.f;
    for (int c = 0; c < 256; c++) a += out_w[c] * fc0_w[c * F_ + f];
    g_v[f] = a;
    if (f == 0) {
        float s = out_b[0];
        for (int c = 0; c < 256; c++) s += out_w[c] * fc0_b[c];
        g_cs = s;
    }
}

// ---------------- Kernel D: out[b] = sum_{n,f} x[b,n,f] * v[f] + cs ----------------
__global__ void pool_out_kernel(float* __restrict__ out) {
    int b = blockIdx.x;
    int tid = threadIdx.x;      // 256
    float vf = g_v[tid & (F_ - 1)];
    const float* p = g_x + (size_t)b * (N_ * F_);
    float a = 0.f;
    #pragma unroll 8
    for (int i = tid; i < N_ * F_; i += 256) a += p[i] * vf;
    __shared__ float s[256];
    s[tid] = a;
    __syncthreads();
    for (int st = 128; st > 0; st >>= 1) {
        if (tid < st) s[tid] += s[tid + st];
        __syncthreads();
    }
    if (tid == 0) out[b] = s[0] + g_cs;
}

// ---------------- launch ----------------
extern "C" void kernel_launch(void* const* d_in, const int* in_sizes, int n_in,
                              void* d_out, int out_size) {
    const float* x      = (const float*)d_in[0];
    const float* dist   = (const float*)d_in[1];
    const float* Wcf_w  = (const float*)d_in[2];
    const float* Wcf_b  = (const float*)d_in[3];
    const float* Wdf_w  = (const float*)d_in[4];
    const float* Wdf_b  = (const float*)d_in[5];
    const float* Wfc_w  = (const float*)d_in[6];
    const float* fc0_w  = (const float*)d_in[7];
    const float* fc0_b  = (const float*)d_in[8];
    const float* out_w  = (const float*)d_in[9];
    const float* out_b  = (const float*)d_in[10];
    float* out = (float*)d_out;

    cudaFuncSetAttribute(dtnn_layers_kernel,
                         cudaFuncAttributeMaxDynamicSharedMemorySize, SMEM_B_BYTES);

    reduce_dist_kernel<<<ROWS, 256>>>(dist);
    dtnn_layers_kernel<<<ROWS / 32, 256, SMEM_B_BYTES>>>(x, Wcf_w, Wcf_b, Wdf_w, Wdf_b, Wfc_w);
    fold_head_kernel<<<1, 128>>>(fc0_w, fc0_b, out_w, out_b);
    pool_out_kernel<<<B_, 256>>>(out);
}

// round 2
// speedup vs baseline: 1.0062x; 1.0062x over previous
#include <cuda_runtime.h>
#include <cuda_bf16.h>
#include <math.h>

// Shapes (fixed by the problem)
#define B_   64
#define N_   128
#define F_   128
#define R_   64
#define H_   256
#define L_   3
#define ROWS (B_*N_)          // 8192

// ---------------- scratch (no allocations allowed) ----------------
__device__ float g_dsum[ROWS * R_];   // 2 MB
__device__ float g_x[ROWS * F_];      // 4 MB
__device__ float g_v[F_];
__device__ float g_cs;

// ---------------- Kernel A: d_sum[b,n,r] = sum_j distance[b,n,j,r] ----------------
// One block per (b,n) row: reduces 128x64 contiguous fp32 (32 KB) -> 64 floats.
__global__ void reduce_dist_kernel(const float* __restrict__ dist) {
    int row = blockIdx.x;                 // 0..8191
    int tid = threadIdx.x;                // 256 threads
    const float4* p = (const float4*)(dist + (size_t)row * (N_ * R_)); // 2048 float4
    float4 acc = make_float4(0.f, 0.f, 0.f, 0.f);
    #pragma unroll
    for (int t = 0; t < 8; t++) {
        float4 v = p[tid + t * 256];
        acc.x += v.x; acc.y += v.y; acc.z += v.z; acc.w += v.w;
    }
    __shared__ float4 s[256];
    s[tid] = acc;
    __syncthreads();
    // quad index of thread tid is (tid % 16); 16 threads share each r-quad
    if (tid < 16) {
        float4 a = s[tid];
        #pragma unroll
        for (int m = 1; m < 16; m++) {
            float4 b = s[tid + 16 * m];
            a.x += b.x; a.y += b.y; a.z += b.z; a.w += b.w;
        }
        ((float4*)(g_dsum + (size_t)row * R_))[tid] = a;
    }
}

// ---------------- Kernel B: fused 3-layer DTNN over 32-row tiles ----------------
// Block: 256 threads (ty = tid/32 in 0..7 -> 4 rows each; tx = tid%32).
// smem: Xs[32][128], Ps[32][256], Ds[32][64], weight staging (padded +4 floats
// per column to keep LDS.128 conflict-free).
#define CFPAD 132   // 128 + 4
#define DFPAD 68    // 64 + 4
#define FCPAD 260   // 256 + 4
#define WS_CF_FLOATS (64 * CFPAD)    // 8448 (also covers fc chunk: 32*260=8320)
#define WS_DF_FLOATS (64 * DFPAD)    // 4352
#define SMEM_B_FLOATS (32*128 + 32*256 + 32*64 + WS_CF_FLOATS + WS_DF_FLOATS)
#define SMEM_B_BYTES  (SMEM_B_FLOATS * 4)   // 108544 B

__global__ __launch_bounds__(256, 2)
void dtnn_layers_kernel(const float* __restrict__ x_in,
                        const float* __restrict__ Wcf_w, const float* __restrict__ Wcf_b,
                        const float* __restrict__ Wdf_w, const float* __restrict__ Wdf_b,
                        const float* __restrict__ Wfc_w) {
    extern __shared__ float sm[];
    float* Xs   = sm;                         // 32*128
    float* Ps   = Xs + 32 * 128;              // 32*256
    float* Ds   = Ps + 32 * 256;              // 32*64
    float* Ws   = Ds + 32 * 64;               // cf / fc staging
    float* Wsdf = Ws + WS_CF_FLOATS;          // df staging

    int tid = threadIdx.x;
    int tx = tid & 31, ty = tid >> 5;
    int row0 = blockIdx.x * 32;

    // load Xs (32x128) and Ds (32x64), fully coalesced
    {
        const float4* xg = (const float4*)(x_in + (size_t)row0 * F_);
        float4* Xs4 = (float4*)Xs;
        #pragma unroll
        for (int t = 0; t < 4; t++) Xs4[tid + t * 256] = xg[tid + t * 256];
        const float4* dg = (const float4*)(g_dsum + (size_t)row0 * R_);
        float4* Ds4 = (float4*)Ds;
        #pragma unroll
        for (int t = 0; t < 2; t++) Ds4[tid + t * 256] = dg[tid + t * 256];
    }
    __syncthreads();

    for (int l = 0; l < L_; l++) {
        const float* wcf = Wcf_w + (size_t)l * H_ * F_;
        const float* wdf = Wdf_w + (size_t)l * H_ * R_;
        const float* bcf = Wcf_b + (size_t)l * H_;
        const float* bdf = Wdf_b + (size_t)l * H_;
        const float* wfc = Wfc_w + (size_t)l * F_ * H_;

        // ---- cf & df GEMMs, fused product -> Ps ----
        for (int cb = 0; cb < H_; cb += 64) {
            // stage cf chunk: 64 cols x 128 k (contiguous slab) -> stride CFPAD
            {
                const float4* g = (const float4*)(wcf + (size_t)cb * F_);
                #pragma unroll
                for (int t = 0; t < 8; t++) {
                    int idx = tid + t * 256;           // 2048 float4
                    int cc = idx >> 5;                 // 32 f4 per col
                    int kq = idx & 31;
                    ((float4*)(Ws + cc * CFPAD))[kq] = g[idx];
                }
                const float4* gd = (const float4*)(wdf + (size_t)cb * R_);
                #pragma unroll
                for (int t = 0; t < 4; t++) {
                    int idx = tid + t * 256;           // 1024 float4
                    int cc = idx >> 4;                 // 16 f4 per col
                    int kq = idx & 15;
                    ((float4*)(Wsdf + cc * DFPAD))[kq] = gd[idx];
                }
            }
            __syncthreads();

            float accD[4][2] = {};
            float accC[4][2] = {};
            // df: K = 64
            #pragma unroll 4
            for (int k = 0; k < R_; k += 4) {
                float4 w0 = *(const float4*)(Wsdf + tx * DFPAD + k);
                float4 w1 = *(const float4*)(Wsdf + (tx + 32) * DFPAD + k);
                #pragma unroll
                for (int i = 0; i < 4; i++) {
                    float4 d = *(const float4*)(Ds + (ty * 4 + i) * R_ + k);
                    accD[i][0] += d.x * w0.x + d.y * w0.y + d.z * w0.z + d.w * w0.w;
                    accD[i][1] += d.x * w1.x + d.y * w1.y + d.z * w1.z + d.w * w1.w;
                }
            }
            // cf: K = 128
            #pragma unroll 4
            for (int k = 0; k < F_; k += 4) {
                float4 w0 = *(const float4*)(Ws + tx * CFPAD + k);
                float4 w1 = *(const float4*)(Ws + (tx + 32) * CFPAD + k);
                #pragma unroll
                for (int i = 0; i < 4; i++) {
                    float4 xv = *(const float4*)(Xs + (ty * 4 + i) * F_ + k);
                    accC[i][0] += xv.x * w0.x + xv.y * w0.y + xv.z * w0.z + xv.w * w0.w;
                    accC[i][1] += xv.x * w1.x + xv.y * w1.y + xv.z * w1.z + xv.w * w1.w;
                }
            }
            #pragma unroll
            for (int j = 0; j < 2; j++) {
                int c = cb + tx + 32 * j;
                float bc = __ldg(bcf + c);
                float bd = 128.0f * __ldg(bdf + c);
                #pragma unroll
                for (int i = 0; i < 4; i++) {
                    Ps[(ty * 4 + i) * H_ + c] = (accC[i][j] + bc) * (accD[i][j] + bd);
                }
            }
            __syncthreads();
        }

        // ---- h = P @ Wfc^T, x = h + tanh(h) -> Xs ----
        for (int fb = 0; fb < F_; fb += 32) {
            // stage fc chunk: 32 cols x 256 k (contiguous slab) -> stride FCPAD
            {
                const float4* g = (const float4*)(wfc + (size_t)fb * H_);
                #pragma unroll
                for (int t = 0; t < 8; t++) {
                    int idx = tid + t * 256;           // 2048 float4
                    int cc = idx >> 6;                 // 64 f4 per col
                    int kq = idx & 63;
                    ((float4*)(Ws + cc * FCPAD))[kq] = g[idx];
                }
            }
            __syncthreads();

            float acc3[4] = {};
            #pragma unroll 4
            for (int k = 0; k < H_; k += 4) {
                float4 w = *(const float4*)(Ws + tx * FCPAD + k);
                #pragma unroll
                for (int i = 0; i < 4; i++) {
                    float4 p = *(const float4*)(Ps + (ty * 4 + i) * H_ + k);
                    acc3[i] += p.x * w.x + p.y * w.y + p.z * w.z + p.w * w.w;
                }
            }
            int f = fb + tx;
            #pragma unroll
            for (int i = 0; i < 4; i++) {
                float h = acc3[i];
                Xs[(ty * 4 + i) * F_ + f] = h + tanhf(h);
            }
            __syncthreads();
        }
    }

    // write final x tile
    {
        float4* xo = (float4*)(g_x + (size_t)row0 * F_);
        const float4* Xs4 = (const float4*)Xs;
        #pragma unroll
        for (int t = 0; t < 4; t++) xo[tid + t * 256] = Xs4[tid + t * 256];
    }
}

// ---------------- Kernel C: fold head (v = out_w @ fc0_w, cs = out_w@fc0_b + out_b) ----------------
__global__ void fold_head_kernel(const float* __restrict__ fc0_w, const float* __restrict__ fc0_b,
                                 const float* __restrict__ out_w, const float* __restrict__ out_b) {
    int f = threadIdx.x;   // 128
    float a = 0.f;
    for (int c = 0; c < 256; c++) a += out_w[c] * fc0_w[c * F_ + f];
    g_v[f] = a;
    if (f == 0) {
        float s = out_b[0];
        for (int c = 0; c < 256; c++) s += out_w[c] * fc0_b[c];
        g_cs = s;
    }
}

// ---------------- Kernel D: out[b] = sum_{n,f} x[b,n,f] * v[f] + cs ----------------
__global__ void pool_out_kernel(float* __restrict__ out) {
    int b = blockIdx.x;
    int tid = threadIdx.x;      // 256
    float vf = g_v[tid & (F_ - 1)];
    const float* p = g_x + (size_t)b * (N_ * F_);
    float a = 0.f;
    #pragma unroll 8
    for (int i = tid; i < N_ * F_; i += 256) a += p[i] * vf;
    __shared__ float s[256];
    s[tid] = a;
    __syncthreads();
    for (int st = 128; st > 0; st >>= 1) {
        if (tid < st) s[tid] += s[tid + st];
        __syncthreads();
    }
    if (tid == 0) out[b] = s[0] + g_cs;
}

// ---------------- launch ----------------
extern "C" void kernel_launch(void* const* d_in, const int* in_sizes, int n_in,
                              void* d_out, int out_size) {
    const float* x      = (const float*)d_in[0];
    const float* dist   = (const float*)d_in[1];
    const float* Wcf_w  = (const float*)d_in[2];
    const float* Wcf_b  = (const float*)d_in[3];
    const float* Wdf_w  = (const float*)d_in[4];
    const float* Wdf_b  = (const float*)d_in[5];
    const float* Wfc_w  = (const float*)d_in[6];
    const float* fc0_w  = (const float*)d_in[7];
    const float* fc0_b  = (const float*)d_in[8];
    const float* out_w  = (const float*)d_in[9];
    const float* out_b  = (const float*)d_in[10];
    float* out = (float*)d_out;

    cudaFuncSetAttribute(dtnn_layers_kernel,
                         cudaFuncAttributeMaxDynamicSharedMemorySize, SMEM_B_BYTES);

    reduce_dist_kernel<<<ROWS, 256>>>(dist);
    dtnn_layers_kernel<<<ROWS / 32, 256, SMEM_B_BYTES>>>(x, Wcf_w, Wcf_b, Wdf_w, Wdf_b, Wfc_w);
    fold_head_kernel<<<1, 128>>>(fc0_w, fc0_b, out_w, out_b);
    pool_out_kernel<<<B_, 256>>>(out);
}

// round 4
// speedup vs baseline: 2.2214x; 2.2076x over previous
#include <cuda_runtime.h>
#include <cstdint>

#define B_   64
#define N_   128
#define F_   128
#define R_   64
#define H_   256
#define L_   3
#define ROWS (B_*N_)

__device__ float g_dsum[ROWS * R_];
__device__ float g_v[F_];
__device__ float g_cs;
__device__ float g_part[128];

__device__ __forceinline__ uint32_t f2tf(float x) {
    uint32_t r; asm("cvt.rna.tf32.f32 %0, %1;" : "=r"(r) : "f"(x)); return r;
}
__device__ __forceinline__ float tanh_fast(float x) {
    float r; asm("tanh.approx.f32 %0, %1;" : "=f"(r) : "f"(x)); return r;
}
__device__ __forceinline__ void mma8(float* d, uint32_t a0, uint32_t a1, uint32_t a2, uint32_t a3,
                                     uint32_t b0, uint32_t b1) {
    asm volatile(
        "mma.sync.aligned.m16n8k8.row.col.f32.tf32.tf32.f32 "
        "{%0,%1,%2,%3},{%4,%5,%6,%7},{%8,%9},{%0,%1,%2,%3};"
        : "+f"(d[0]), "+f"(d[1]), "+f"(d[2]), "+f"(d[3])
        : "r"(a0), "r"(a1), "r"(a2), "r"(a3), "r"(b0), "r"(b1));
}
__device__ __forceinline__ uint32_t ldw(const float* p) { return *(const uint32_t*)p; }

// Stage [RT x KC] fp32 (src row stride SS) -> smem row-major stride DS, tf32-rounded.
template<int RT, int KC, int SS, int DS>
__device__ __forceinline__ void stage(float* dst, const float* __restrict__ src, int tid) {
    constexpr int K4 = KC / 4;
    #pragma unroll
    for (int idx = tid; idx < RT * K4; idx += 256) {
        int row = idx / K4;
        int c4 = (idx - row * K4) * 4;
        float4 v = *(const float4*)(src + (size_t)row * SS + c4);
        uint4 o;
        o.x = f2tf(v.x); o.y = f2tf(v.y); o.z = f2tf(v.z); o.w = f2tf(v.w);
        *(uint4*)(dst + row * DS + c4) = o;
    }
}

// ---------------- Kernel A: d_sum row reduction (HBM-bound) ----------------
__global__ void reduce_dist_kernel(const float* __restrict__ dist) {
    int row = blockIdx.x;
    int tid = threadIdx.x;
    const float4* p = (const float4*)(dist + (size_t)row * (N_ * R_));
    float4 acc = make_float4(0.f, 0.f, 0.f, 0.f);
    #pragma unroll
    for (int t = 0; t < 8; t++) {
        float4 v = p[tid + t * 256];
        acc.x += v.x; acc.y += v.y; acc.z += v.z; acc.w += v.w;
    }
    __shared__ float4 s[256];
    s[tid] = acc;
    __syncthreads();
    if (tid < 16) {
        float4 a = s[tid];
        #pragma unroll
        for (int m = 1; m < 16; m++) {
            float4 b = s[tid + 16 * m];
            a.x += b.x; a.y += b.y; a.z += b.z; a.w += b.w;
        }
        ((float4*)(g_dsum + (size_t)row * R_))[tid] = a;
    }
}

// ---------------- Kernel C: fold head ----------------
__global__ void fold_head_kernel(const float* __restrict__ fc0_w, const float* __restrict__ fc0_b,
                                 const float* __restrict__ out_w, const float* __restrict__ out_b) {
    int f = threadIdx.x;
    float a = 0.f;
    #pragma unroll 8
    for (int c = 0; c < 256; c++) a += out_w[c] * fc0_w[c * F_ + f];
    g_v[f] = a;
    if (f == 0) {
        float s = out_b[0];
        for (int c = 0; c < 256; c++) s += out_w[c] * fc0_b[c];
        g_cs = s;
    }
}

// ---------------- Kernel B: mma.sync tf32 fused 3 layers + pooling ----------------
// 128 CTAs x 64 rows. smem word offsets:
enum {
    OXS = 0,          // Xs [64][132]
    ODS = 8448,       // Ds [64][68]
    OPB = 12800,      // Pb [64][68]
    OWA = 17152,      // Wa: cf chunk [64][132] / fc chunk [128][68]
    OWD = 25856,      // Wd [64][68]
    OBC = 30208,      // bcf [256]
    OBD = 30464,      // bdf [256]
    OVV = 30720,      // v [128]
    ORD = 30848,      // reduce [256]
    TOTW = 31104
};
#define SMEMB (TOTW * 4)

__global__ __launch_bounds__(256, 1)
void dtnn_mma_kernel(const float* __restrict__ x,
                     const float* __restrict__ Wcf_w, const float* __restrict__ Wcf_b,
                     const float* __restrict__ Wdf_w, const float* __restrict__ Wdf_b,
                     const float* __restrict__ Wfc_w) {
    extern __shared__ float sm[];
    float* Xs = sm + OXS; float* Ds = sm + ODS; float* Pb = sm + OPB;
    float* Wa = sm + OWA; float* Wd = sm + OWD;
    float* bc = sm + OBC; float* bd = sm + OBD;
    float* vv = sm + OVV; float* rd = sm + ORD;

    int tid = threadIdx.x, lane = tid & 31, w = tid >> 5;
    int g = lane >> 2, t = lane & 3;
    int wm = w & 1, wn = w >> 1;          // warp grid: 2 (M) x 4 (N)
    int rows0 = blockIdx.x * 64;

    stage<64, 128, 128, 132>(Xs, x + (size_t)rows0 * 128, tid);
    stage<64, 64, 64, 68>(Ds, g_dsum + (size_t)rows0 * 64, tid);
    if (tid < 128) vv[tid] = g_v[tid];

    float pool = 0.f;
    for (int l = 0; l < L_; l++) {
        const float* wcf = Wcf_w + (size_t)l * H_ * F_;
        const float* wdf = Wdf_w + (size_t)l * H_ * R_;
        const float* wfc = Wfc_w + (size_t)l * F_ * H_;
        bc[tid] = Wcf_b[l * H_ + tid];
        bd[tid] = Wdf_b[l * H_ + tid];

        float hacc[2][4][4] = {};   // fc accum: warp tile 32x32 over [64][128]

        for (int c = 0; c < 4; c++) {
            int hc = c * 64;
            stage<64, 128, 128, 132>(Wa, wcf + (size_t)hc * 128, tid);
            stage<64, 64, 64, 68>(Wd, wdf + (size_t)hc * 64, tid);
            __syncthreads();

            float cf[2][2][4] = {}, df[2][2][4] = {};
            // cf: [64x128] @ WcfT chunk -> 64x64; warp tile 32x16
            #pragma unroll
            for (int ks = 0; ks < 16; ks++) {
                int k0 = ks * 8;
                uint32_t A[2][4];
                #pragma unroll
                for (int mt = 0; mt < 2; mt++) {
                    const float* ba = Xs + (wm * 32 + mt * 16 + g) * 132 + k0 + t;
                    A[mt][0] = ldw(ba); A[mt][1] = ldw(ba + 8 * 132);
                    A[mt][2] = ldw(ba + 4); A[mt][3] = ldw(ba + 8 * 132 + 4);
                }
                #pragma unroll
                for (int nt = 0; nt < 2; nt++) {
                    const float* bb = Wa + (wn * 16 + nt * 8 + g) * 132 + k0 + t;
                    uint32_t b0 = ldw(bb), b1 = ldw(bb + 4);
                    mma8(cf[0][nt], A[0][0], A[0][1], A[0][2], A[0][3], b0, b1);
                    mma8(cf[1][nt], A[1][0], A[1][1], A[1][2], A[1][3], b0, b1);
                }
            }
            // df: [64x64] @ WdfT chunk -> 64x64
            #pragma unroll
            for (int ks = 0; ks < 8; ks++) {
                int k0 = ks * 8;
                uint32_t A[2][4];
                #pragma unroll
                for (int mt = 0; mt < 2; mt++) {
                    const float* ba = Ds + (wm * 32 + mt * 16 + g) * 68 + k0 + t;
                    A[mt][0] = ldw(ba); A[mt][1] = ldw(ba + 8 * 68);
                    A[mt][2] = ldw(ba + 4); A[mt][3] = ldw(ba + 8 * 68 + 4);
                }
                #pragma unroll
                for (int nt = 0; nt < 2; nt++) {
                    const float* bb = Wd + (wn * 16 + nt * 8 + g) * 68 + k0 + t;
                    uint32_t b0 = ldw(bb), b1 = ldw(bb + 4);
                    mma8(df[0][nt], A[0][0], A[0][1], A[0][2], A[0][3], b0, b1);
                    mma8(df[1][nt], A[1][0], A[1][1], A[1][2], A[1][3], b0, b1);
                }
            }
            __syncthreads();   // done reading Wa/Wd

            // P = (cf+bc)*(df+128*bd) -> Pb (tf32 bits)
            #pragma unroll
            for (int mt = 0; mt < 2; mt++)
            #pragma unroll
            for (int nt = 0; nt < 2; nt++) {
                int col = wn * 16 + nt * 8 + 2 * t;
                int row = wm * 32 + mt * 16 + g;
                float b0c = bc[hc + col], b1c = bc[hc + col + 1];
                float b0d = 128.f * bd[hc + col], b1d = 128.f * bd[hc + col + 1];
                float* f4 = cf[mt][nt];
                float* d4 = df[mt][nt];
                uint2 p01, p23;
                p01.x = f2tf((f4[0] + b0c) * (d4[0] + b0d));
                p01.y = f2tf((f4[1] + b1c) * (d4[1] + b1d));
                p23.x = f2tf((f4[2] + b0c) * (d4[2] + b0d));
                p23.y = f2tf((f4[3] + b1c) * (d4[3] + b1d));
                *(uint2*)(Pb + row * 68 + col) = p01;
                *(uint2*)(Pb + (row + 8) * 68 + col) = p23;
            }
            // stage Wfc chunk: Wa[f][k] = wfc[f*256 + hc + k], [128][68]
            stage<128, 64, 256, 68>(Wa, wfc + hc, tid);
            __syncthreads();

            // fc: accumulate [64x64chunk] @ WfcT -> hacc (warp 32x32)
            #pragma unroll
            for (int ks = 0; ks < 8; ks++) {
                int k0 = ks * 8;
                uint32_t A[2][4];
                #pragma unroll
                for (int mt = 0; mt < 2; mt++) {
                    const float* ba = Pb + (wm * 32 + mt * 16 + g) * 68 + k0 + t;
                    A[mt][0] = ldw(ba); A[mt][1] = ldw(ba + 8 * 68);
                    A[mt][2] = ldw(ba + 4); A[mt][3] = ldw(ba + 8 * 68 + 4);
                }
                #pragma unroll
                for (int nt = 0; nt < 4; nt++) {
                    const float* bb = Wa + (wn * 32 + nt * 8 + g) * 68 + k0 + t;
                    uint32_t b0 = ldw(bb), b1 = ldw(bb + 4);
                    mma8(hacc[0][nt], A[0][0], A[0][1], A[0][2], A[0][3], b0, b1);
                    mma8(hacc[1][nt], A[1][0], A[1][1], A[1][2], A[1][3], b0, b1);
                }
            }
            __syncthreads();   // before next chunk overwrites Wa/Wd/Pb
        }

        // layer epilogue: x = h + tanh(h)
        if (l < 2) {
            #pragma unroll
            for (int mt = 0; mt < 2; mt++)
            #pragma unroll
            for (int nt = 0; nt < 4; nt++) {
                int row = wm * 32 + mt * 16 + g;
                int col = wn * 32 + nt * 8 + 2 * t;
                float* h4 = hacc[mt][nt];
                uint2 x01, x23;
                float v0 = h4[0] + tanh_fast(h4[0]);
                float v1 = h4[1] + tanh_fast(h4[1]);
                float v2 = h4[2] + tanh_fast(h4[2]);
                float v3 = h4[3] + tanh_fast(h4[3]);
                x01.x = f2tf(v0); x01.y = f2tf(v1);
                x23.x = f2tf(v2); x23.y = f2tf(v3);
                *(uint2*)(Xs + row * 132 + col) = x01;
                *(uint2*)(Xs + (row + 8) * 132 + col) = x23;
            }
            __syncthreads();
        } else {
            #pragma unroll
            for (int mt = 0; mt < 2; mt++)
            #pragma unroll
            for (int nt = 0; nt < 4; nt++) {
                int col = wn * 32 + nt * 8 + 2 * t;
                float* h4 = hacc[mt][nt];
                pool += (h4[0] + tanh_fast(h4[0])) * vv[col];
                pool += (h4[1] + tanh_fast(h4[1])) * vv[col + 1];
                pool += (h4[2] + tanh_fast(h4[2])) * vv[col];
                pool += (h4[3] + tanh_fast(h4[3])) * vv[col + 1];
            }
            rd[tid] = pool;
            __syncthreads();
            for (int s = 128; s > 0; s >>= 1) {
                if (tid < s) rd[tid] += rd[tid + s];
                __syncthreads();
            }
            if (tid == 0) g_part[blockIdx.x] = rd[0];
        }
    }
}

// ---------------- Kernel D: final pooling combine ----------------
__global__ void pool_final_kernel(float* __restrict__ out) {
    int b = threadIdx.x;   // 64
    out[b] = g_part[2 * b] + g_part[2 * b + 1] + g_cs;
}

// ---------------- launch ----------------
extern "C" void kernel_launch(void* const* d_in, const int* in_sizes, int n_in,
                              void* d_out, int out_size) {
    const float* x     = (const float*)d_in[0];
    const float* dist  = (const float*)d_in[1];
    const float* Wcf_w = (const float*)d_in[2];
    const float* Wcf_b = (const float*)d_in[3];
    const float* Wdf_w = (const float*)d_in[4];
    const float* Wdf_b = (const float*)d_in[5];
    const float* Wfc_w = (const float*)d_in[6];
    const float* fc0_w = (const float*)d_in[7];
    const float* fc0_b = (const float*)d_in[8];
    const float* out_w = (const float*)d_in[9];
    const float* out_b = (const float*)d_in[10];
    float* out = (float*)d_out;

    cudaFuncSetAttribute(dtnn_mma_kernel,
                         cudaFuncAttributeMaxDynamicSharedMemorySize, SMEMB);

    reduce_dist_kernel<<<ROWS, 256>>>(dist);
    fold_head_kernel<<<1, 128>>>(fc0_w, fc0_b, out_w, out_b);
    dtnn_mma_kernel<<<128, 256, SMEMB>>>(x, Wcf_w, Wcf_b, Wdf_w, Wdf_b, Wfc_w);
    pool_final_kernel<<<1, 64>>>(out);
}